// round 2
// baseline (speedup 1.0000x reference)
#include <cuda_runtime.h>
#include <math.h>

#define BB 8192

// ---------------- intermediate buffers (static __device__, per allocation rules) ----------
__device__ float g_xT[3 * 28 * 28 * BB];     // input transposed  [c][h][w][b]
__device__ float g_a1[8 * 13 * 13 * BB];     // layer1 out (full 13x13 valid)
__device__ float g_bufA[16 * 12 * 12 * BB];  // ping (compact 12x12 valid region)
__device__ float g_bufB[16 * 12 * 12 * BB];  // pong
__device__ float g_a6[32 * 5 * 5 * BB];      // layer6 out (compact 5x5 valid)

// ---------------- f32x2 helpers -----------------------------------------------------------
__device__ __forceinline__ void fma2(unsigned long long& d, unsigned long long a,
                                     unsigned long long b) {
    asm("fma.rn.f32x2 %0, %1, %2, %0;" : "+l"(d) : "l"(a), "l"(b));
}
__device__ __forceinline__ unsigned long long pack2(float lo, float hi) {
    unsigned long long r;
    asm("mov.b64 %0, {%1, %2};" : "=l"(r) : "f"(lo), "f"(hi));
    return r;
}
__device__ __forceinline__ float2 unpack2(unsigned long long v) {
    float2 f;
    asm("mov.b64 {%0, %1}, %2;" : "=f"(f.x), "=f"(f.y) : "l"(v));
    return f;
}

// ---------------- transpose: x (B, 3*28*28) NCHW -> xT [c*h*w][B] --------------------------
__global__ void __launch_bounds__(256) transpose_kernel(const float* __restrict__ x) {
    __shared__ float tile[32][33];
    int p0 = blockIdx.x * 32;
    int b0 = blockIdx.y * 32;
    int tx = threadIdx.x, ty = threadIdx.y;  // (32, 8)
#pragma unroll
    for (int j = 0; j < 4; j++) {
        int p = p0 + tx;
        int bb = b0 + ty + 8 * j;
        tile[ty + 8 * j][tx] = (p < 2352) ? x[bb * 2352 + p] : 0.f;
    }
    __syncthreads();
#pragma unroll
    for (int j = 0; j < 4; j++) {
        int p = p0 + ty + 8 * j;
        int bb = b0 + tx;
        if (p < 2352) g_xT[p * BB + bb] = tile[tx][ty + 8 * j];
    }
}

// ---------------- layer 1: cin=3, k=5, s=2, pad=1, 28x28 -> 13x13, cout=8, ReLU ------------
// weight quirk: Weff(ci,kh,kw,co) = K1flat[(ci*25 + kh*5 + kw)*8 + co]
__global__ void __launch_bounds__(256) conv1_kernel(const float* __restrict__ Kw) {
    __shared__ __align__(16) float ws[600];
    int tid = threadIdx.x;
    for (int i = tid; i < 600; i += 256) ws[i] = Kw[i];
    __syncthreads();
    const unsigned long long* ws2 = reinterpret_cast<const unsigned long long*>(ws);

    int b = blockIdx.x * 64 + (tid & 63);
    int cg = tid >> 6;  // channel pair: co = 2*cg, 2*cg+1
    int oh = blockIdx.y;

    unsigned long long acc[13];
#pragma unroll
    for (int ow = 0; ow < 13; ow++) acc[ow] = 0ULL;

    for (int ci = 0; ci < 3; ci++) {
#pragma unroll
        for (int kh = 0; kh < 5; kh++) {
            int ih = 2 * oh + kh - 1;  // -1..27
            unsigned long long r2[28];
            if (ih >= 0 && ih < 28) {
                const float* rowp = g_xT + (ci * 28 + ih) * 28 * BB + b;
#pragma unroll
                for (int iw = 0; iw < 28; iw++) {
                    float v = rowp[iw * BB];
                    r2[iw] = pack2(v, v);
                }
            } else {
#pragma unroll
                for (int iw = 0; iw < 28; iw++) r2[iw] = 0ULL;
            }
#pragma unroll
            for (int kw = 0; kw < 5; kw++) {
                unsigned long long w = ws2[(((ci * 5 + kh) * 5 + kw) * 8 + 2 * cg) >> 1];
#pragma unroll
                for (int ow = 0; ow < 13; ow++) {
                    int iw = 2 * ow + kw - 1;
                    if (iw >= 0) fma2(acc[ow], r2[iw], w);
                }
            }
        }
    }
#pragma unroll
    for (int ow = 0; ow < 13; ow++) {
        float2 v = unpack2(acc[ow]);
        int co = 2 * cg;
        g_a1[((co * 13 + oh) * 13 + ow) * BB + b] = fmaxf(v.x, 0.f);
        g_a1[(((co + 1) * 13 + oh) * 13 + ow) * BB + b] = fmaxf(v.y, 0.f);
    }
}

// ---------------- 3x3 layers (2..5): s=1, pad=1, out 12x12 valid, cout=16, ReLU ------------
// SRC/DST: 0 = g_a1, 1 = g_bufA, 2 = g_bufB
__device__ __forceinline__ float* buf_ptr(int id) {
    return id == 0 ? g_a1 : (id == 1 ? g_bufA : g_bufB);
}

template <int CIN, int IN_H, int SRC, int DST>
__global__ void __launch_bounds__(256) conv3_kernel(const float* __restrict__ Kw) {
    constexpr int COUT = 16;
    __shared__ __align__(16) float ws[CIN * 9 * COUT];
    int tid = threadIdx.x;
    for (int i = tid; i < CIN * 9 * COUT; i += 256) ws[i] = Kw[i];
    __syncthreads();
    const unsigned long long* ws2 = reinterpret_cast<const unsigned long long*>(ws);

    const float* in = buf_ptr(SRC);
    float* out = buf_ptr(DST);

    int b = blockIdx.x * 64 + (tid & 63);
    int cg = tid >> 6;
    int co0 = cg * 4;  // 4 output channels = 2 f32x2 pairs
    int oh = blockIdx.y;

    unsigned long long acc[2][12];
#pragma unroll
    for (int p = 0; p < 2; p++)
#pragma unroll
        for (int ow = 0; ow < 12; ow++) acc[p][ow] = 0ULL;

    for (int ci = 0; ci < CIN; ci++) {
#pragma unroll
        for (int kh = 0; kh < 3; kh++) {
            int ih = oh + kh - 1;  // -1..12 ; row 12 is zero when IN_H==12 (quirk)
            unsigned long long r2[13];
            if (ih >= 0 && ih < IN_H) {
                const float* rowp = in + (ci * IN_H + ih) * IN_H * BB + b;
#pragma unroll
                for (int iw = 0; iw < 13; iw++) {
                    float v = (iw < IN_H) ? rowp[iw * BB] : 0.f;
                    r2[iw] = pack2(v, v);
                }
            } else {
#pragma unroll
                for (int iw = 0; iw < 13; iw++) r2[iw] = 0ULL;
            }
#pragma unroll
            for (int kw = 0; kw < 3; kw++) {
                int wbase = (((ci * 3 + kh) * 3 + kw) * COUT + co0) >> 1;
                unsigned long long w0 = ws2[wbase];
                unsigned long long w1 = ws2[wbase + 1];
#pragma unroll
                for (int ow = 0; ow < 12; ow++) {
                    int iw = ow + kw - 1;
                    if (iw >= 0) {
                        fma2(acc[0][ow], r2[iw], w0);
                        fma2(acc[1][ow], r2[iw], w1);
                    }
                }
            }
        }
    }
#pragma unroll
    for (int p = 0; p < 2; p++) {
#pragma unroll
        for (int ow = 0; ow < 12; ow++) {
            float2 v = unpack2(acc[p][ow]);
            int co = co0 + 2 * p;
            out[((co * 12 + oh) * 12 + ow) * BB + b] = fmaxf(v.x, 0.f);
            out[(((co + 1) * 12 + oh) * 12 + ow) * BB + b] = fmaxf(v.y, 0.f);
        }
    }
}

// ---------------- layer 6: cin=16, k=5, s=2, pad=1, 12x12(+zeros) -> 5x5 valid, cout=32 ----
__global__ void __launch_bounds__(256) conv6_kernel(const float* __restrict__ Kw) {
    __shared__ __align__(16) float ws[800];
    int tid = threadIdx.x;
    int b = blockIdx.x * 64 + (tid & 63);
    int cg = tid >> 6;
    int co0 = cg * 8;  // 8 output channels = 4 f32x2 pairs
    int oh = blockIdx.y;  // 0..4

    unsigned long long acc[4][5];
#pragma unroll
    for (int p = 0; p < 4; p++)
#pragma unroll
        for (int ow = 0; ow < 5; ow++) acc[p][ow] = 0ULL;

    const unsigned long long* ws2 = reinterpret_cast<const unsigned long long*>(ws);

    for (int ci = 0; ci < 16; ci++) {
        if (ci > 0) __syncthreads();
        for (int i = tid; i < 800; i += 256) ws[i] = Kw[ci * 800 + i];
        __syncthreads();
#pragma unroll
        for (int kh = 0; kh < 5; kh++) {
            int ih = 2 * oh + kh - 1;  // -1..11 (row 12 never touched)
            unsigned long long r2[12];
            if (ih >= 0 && ih < 12) {
                const float* rowp = g_bufB + (ci * 12 + ih) * 12 * BB + b;
#pragma unroll
                for (int iw = 0; iw < 12; iw++) {
                    float v = rowp[iw * BB];
                    r2[iw] = pack2(v, v);
                }
            } else {
#pragma unroll
                for (int iw = 0; iw < 12; iw++) r2[iw] = 0ULL;
            }
#pragma unroll
            for (int kw = 0; kw < 5; kw++) {
                int wbase = ((kh * 5 + kw) * 32 + co0) >> 1;
                unsigned long long w0 = ws2[wbase];
                unsigned long long w1 = ws2[wbase + 1];
                unsigned long long w2 = ws2[wbase + 2];
                unsigned long long w3 = ws2[wbase + 3];
#pragma unroll
                for (int ow = 0; ow < 5; ow++) {
                    int iw = 2 * ow + kw - 1;
                    if (iw >= 0) {
                        fma2(acc[0][ow], r2[iw], w0);
                        fma2(acc[1][ow], r2[iw], w1);
                        fma2(acc[2][ow], r2[iw], w2);
                        fma2(acc[3][ow], r2[iw], w3);
                    }
                }
            }
        }
    }
    // no ReLU on layer 6
#pragma unroll
    for (int p = 0; p < 4; p++) {
#pragma unroll
        for (int ow = 0; ow < 5; ow++) {
            float2 v = unpack2(acc[p][ow]);
            int co = co0 + 2 * p;
            g_a6[((co * 5 + oh) * 5 + ow) * BB + b] = v.x;
            g_a6[(((co + 1) * 5 + oh) * 5 + ow) * BB + b] = v.y;
        }
    }
}

// ---------------- FC (1152->10, only 800 nonzero inputs) + softmax -------------------------
__global__ void __launch_bounds__(256) fc_kernel(const float* __restrict__ Wfc,
                                                 const float* __restrict__ bfc,
                                                 float* __restrict__ out) {
    __shared__ __align__(16) float Wp[8000];  // [k'][cls], k' = co*25+oh*5+ow over valid 5x5
    __shared__ float red[4][64][10];
    int tid = threadIdx.x;
    for (int i = tid; i < 8000; i += 256) {
        int kp = i / 10, cls = i % 10;
        int co = kp / 25, rem = kp % 25, r = rem / 5, c = rem % 5;
        Wp[i] = Wfc[cls * 1152 + co * 36 + r * 6 + c];  // 6x6 layout, zeros at row/col 5
    }
    __syncthreads();
    const unsigned long long* Wp2 = reinterpret_cast<const unsigned long long*>(Wp);

    int bsub = tid & 63;
    int g = tid >> 6;  // k'-split group
    int b = blockIdx.x * 64 + bsub;

    unsigned long long lg[5] = {0ULL, 0ULL, 0ULL, 0ULL, 0ULL};
    int k0 = g * 200;
    for (int kp = k0; kp < k0 + 200; kp++) {
        float v = g_a6[kp * BB + b];
        unsigned long long v2 = pack2(v, v);
#pragma unroll
        for (int c = 0; c < 5; c++) fma2(lg[c], v2, Wp2[kp * 5 + c]);
    }
#pragma unroll
    for (int c = 0; c < 5; c++) {
        float2 f = unpack2(lg[c]);
        red[g][bsub][2 * c] = f.x;
        red[g][bsub][2 * c + 1] = f.y;
    }
    __syncthreads();
    if (g == 0) {
        float logits[10];
#pragma unroll
        for (int c = 0; c < 10; c++)
            logits[c] = red[0][bsub][c] + red[1][bsub][c] + red[2][bsub][c] + red[3][bsub][c] +
                        bfc[c];
        float m = logits[0];
#pragma unroll
        for (int c = 1; c < 10; c++) m = fmaxf(m, logits[c]);
        float s = 0.f;
#pragma unroll
        for (int c = 0; c < 10; c++) {
            float e = expf(logits[c] - m);
            logits[c] = e;
            s += e;
        }
        float inv = 1.f / s;
#pragma unroll
        for (int c = 0; c < 10; c++) out[b * 10 + c] = logits[c] * inv;
    }
}

// ---------------- launch -------------------------------------------------------------------
extern "C" void kernel_launch(void* const* d_in, const int* in_sizes, int n_in, void* d_out,
                              int out_size) {
    const float* x = (const float*)d_in[0];
    const float* K1 = (const float*)d_in[1];
    const float* K2 = (const float*)d_in[2];
    const float* K3 = (const float*)d_in[3];
    const float* K4 = (const float*)d_in[4];
    const float* K5 = (const float*)d_in[5];
    const float* K6 = (const float*)d_in[6];
    const float* Wfc = (const float*)d_in[7];
    const float* bfc = (const float*)d_in[8];
    float* out = (float*)d_out;

    transpose_kernel<<<dim3(74, 256), dim3(32, 8)>>>(x);
    conv1_kernel<<<dim3(128, 13), 256>>>(K1);
    conv3_kernel<8, 13, 0, 1><<<dim3(128, 12), 256>>>(K2);   // a1  -> bufA
    conv3_kernel<16, 12, 1, 2><<<dim3(128, 12), 256>>>(K3);  // bufA -> bufB
    conv3_kernel<16, 12, 2, 1><<<dim3(128, 12), 256>>>(K4);  // bufB -> bufA
    conv3_kernel<16, 12, 1, 2><<<dim3(128, 12), 256>>>(K5);  // bufA -> bufB
    conv6_kernel<<<dim3(128, 5), 256>>>(K6);                 // bufB -> a6
    fc_kernel<<<128, 256>>>(Wfc, bfc, out);
}

// round 5
// speedup vs baseline: 1.1026x; 1.1026x over previous
#include <cuda_runtime.h>
#include <math.h>

#define BB 8192

// ---------------- intermediate buffers ----------------------------------------------------
__device__ float g_xT[3 * 28 * 28 * BB];     // input transposed  [c][h][w][b]
__device__ float g_a1[8 * 13 * 13 * BB];     // layer1 out (full 13x13 valid)
__device__ float g_bufA[16 * 12 * 12 * BB];  // ping (compact 12x12 valid region)
__device__ float g_bufB[16 * 12 * 12 * BB];  // pong
__device__ float g_a6[32 * 5 * 5 * BB];      // layer6 out (compact 5x5 valid)

typedef unsigned long long u64;

// ---------------- f32x2 helpers -----------------------------------------------------------
__device__ __forceinline__ void fma2(u64& d, u64 a, u64 b) {
    asm("fma.rn.f32x2 %0, %1, %2, %0;" : "+l"(d) : "l"(a), "l"(b));
}
__device__ __forceinline__ u64 pack2(float lo, float hi) {
    u64 r;
    asm("mov.b64 %0, {%1, %2};" : "=l"(r) : "f"(lo), "f"(hi));
    return r;
}
__device__ __forceinline__ float2 unpack2(u64 v) {
    float2 f;
    asm("mov.b64 {%0, %1}, %2;" : "=f"(f.x), "=f"(f.y) : "l"(v));
    return f;
}
__device__ __forceinline__ u64 ldg2(const float* p) {
    return *reinterpret_cast<const u64*>(p);
}

// ---------------- transpose: x (B, 3*28*28) NCHW -> xT [c*h*w][B] --------------------------
__global__ void __launch_bounds__(256) transpose_kernel(const float* __restrict__ x) {
    __shared__ float tile[32][33];
    int p0 = blockIdx.x * 32;
    int b0 = blockIdx.y * 32;
    int tx = threadIdx.x, ty = threadIdx.y;  // (32, 8)
#pragma unroll
    for (int j = 0; j < 4; j++) {
        int p = p0 + tx;
        int bb = b0 + ty + 8 * j;
        tile[ty + 8 * j][tx] = (p < 2352) ? x[bb * 2352 + p] : 0.f;
    }
    __syncthreads();
#pragma unroll
    for (int j = 0; j < 4; j++) {
        int p = p0 + ty + 8 * j;
        int bb = b0 + tx;
        if (p < 2352) g_xT[p * BB + bb] = tile[tx][ty + 8 * j];
    }
}

// ---------------- layer 1: cin=3, k=5, s=2, pad=1, 28x28 -> 13x13, cout=8, ReLU ------------
// weights consumed in stored flat order: Kw[(ci*25 + kh*5 + kw)*8 + co]
template <int OWG>
__device__ __forceinline__ void conv1_body(const u64* __restrict__ ws2, int ow0, int b, int oh) {
    constexpr int S = 2 * OWG + 3;  // input span
    u64 acc[8][OWG];
#pragma unroll
    for (int co = 0; co < 8; co++)
#pragma unroll
        for (int ow = 0; ow < OWG; ow++) acc[co][ow] = 0ULL;

    for (int ci = 0; ci < 3; ci++) {
#pragma unroll
        for (int kh = 0; kh < 5; kh++) {
            int ih = 2 * oh + kh - 1;  // -1..27
            bool rowok = (ih >= 0) && (ih < 28);
            const float* rowp = g_xT + ((ci * 28 + ih) * 28 + (2 * ow0 - 1)) * BB + b;
            u64 r[S];
#pragma unroll
            for (int j = 0; j < S; j++) {
                int iw = 2 * ow0 - 1 + j;
                r[j] = (rowok && iw >= 0 && iw < 28) ? ldg2(rowp + j * BB) : 0ULL;
            }
#pragma unroll
            for (int kw = 0; kw < 5; kw++) {
                int base = ((ci * 5 + kh) * 5 + kw) * 8;
#pragma unroll
                for (int co = 0; co < 8; co++) {
                    u64 w = ws2[base + co];
#pragma unroll
                    for (int ow = 0; ow < OWG; ow++) fma2(acc[co][ow], r[2 * ow + kw], w);
                }
            }
        }
    }
#pragma unroll
    for (int co = 0; co < 8; co++)
#pragma unroll
        for (int ow = 0; ow < OWG; ow++) {
            float2 v = unpack2(acc[co][ow]);
            float2 o;
            o.x = fmaxf(v.x, 0.f);
            o.y = fmaxf(v.y, 0.f);
            *reinterpret_cast<float2*>(g_a1 + ((co * 13 + oh) * 13 + ow0 + ow) * BB + b) = o;
        }
}

__global__ void __launch_bounds__(96) conv1_kernel(const float* __restrict__ Kw) {
    __shared__ u64 ws2[600];
    int tid = threadIdx.y * 32 + threadIdx.x;
    for (int i = tid; i < 600; i += 96) {
        float w = Kw[i];
        ws2[i] = pack2(w, w);
    }
    __syncthreads();
    int b = blockIdx.x * 64 + threadIdx.x * 2;
    int oh = blockIdx.y;
    int ty = threadIdx.y;  // 0..2, warp-granular
    if (ty == 0) conv1_body<4>(ws2, 0, b, oh);
    else if (ty == 1) conv1_body<4>(ws2, 4, b, oh);
    else conv1_body<5>(ws2, 8, b, oh);
}

// ---------------- 3x3 layers (2..5): s=1, pad=1, out 12x12 valid, cout=16, ReLU ------------
// SRC/DST: 0 = g_a1, 1 = g_bufA, 2 = g_bufB
__device__ __forceinline__ float* buf_ptr(int id) {
    return id == 0 ? g_a1 : (id == 1 ? g_bufA : g_bufB);
}

template <int CIN, int IN_H, int SRC, int DST>
__global__ void __launch_bounds__(192) conv3_kernel(const float* __restrict__ Kw) {
    constexpr int NW = CIN * 9 * 16;
    __shared__ u64 ws2[NW];
    int tid = threadIdx.y * 32 + threadIdx.x;
    for (int i = tid; i < NW; i += 192) {
        float w = Kw[i];
        ws2[i] = pack2(w, w);
    }
    __syncthreads();

    const float* in = buf_ptr(SRC);
    float* out = buf_ptr(DST);

    int ty = threadIdx.y;        // 0..5
    int co0 = (ty / 3) * 8;      // 8 output channels per thread
    int ow0 = (ty % 3) * 4;      // 4 output columns per thread
    int b = blockIdx.x * 64 + threadIdx.x * 2;
    int oh = blockIdx.y;

    u64 acc[8][4];
#pragma unroll
    for (int co = 0; co < 8; co++)
#pragma unroll
        for (int ow = 0; ow < 4; ow++) acc[co][ow] = 0ULL;

    for (int ci = 0; ci < CIN; ci++) {
#pragma unroll
        for (int kh = 0; kh < 3; kh++) {
            int ih = oh + kh - 1;  // -1..12 ; row IN_H..12 zero (quirk)
            bool rowok = (ih >= 0) && (ih < IN_H);
            const float* rowp = in + ((ci * IN_H + ih) * IN_H + (ow0 - 1)) * BB + b;
            u64 r[6];
#pragma unroll
            for (int j = 0; j < 6; j++) {
                int iw = ow0 - 1 + j;
                r[j] = (rowok && iw >= 0 && iw < IN_H) ? ldg2(rowp + j * BB) : 0ULL;
            }
#pragma unroll
            for (int kw = 0; kw < 3; kw++) {
                int base = ((ci * 3 + kh) * 3 + kw) * 16 + co0;
#pragma unroll
                for (int co = 0; co < 8; co++) {
                    u64 w = ws2[base + co];
#pragma unroll
                    for (int ow = 0; ow < 4; ow++) fma2(acc[co][ow], r[ow + kw], w);
                }
            }
        }
    }
#pragma unroll
    for (int co = 0; co < 8; co++)
#pragma unroll
        for (int ow = 0; ow < 4; ow++) {
            float2 v = unpack2(acc[co][ow]);
            float2 o;
            o.x = fmaxf(v.x, 0.f);
            o.y = fmaxf(v.y, 0.f);
            *reinterpret_cast<float2*>(out + (((co0 + co) * 12 + oh) * 12 + ow0 + ow) * BB + b) =
                o;
        }
}

// ---------------- layer 6: cin=16, k=5, s=2, pad=1, 12x12 -> 5x5 valid, cout=32, no ReLU ---
__global__ void __launch_bounds__(128) conv6_kernel(const float* __restrict__ Kw) {
    __shared__ u64 ws2[800];
    int tid = threadIdx.y * 32 + threadIdx.x;
    int co0 = threadIdx.y * 8;  // 8 of 32 output channels per thread
    int b = blockIdx.x * 64 + threadIdx.x * 2;
    int oh = blockIdx.y;  // 0..4

    u64 acc[8][5];
#pragma unroll
    for (int co = 0; co < 8; co++)
#pragma unroll
        for (int ow = 0; ow < 5; ow++) acc[co][ow] = 0ULL;

    for (int ci = 0; ci < 16; ci++) {
        if (ci > 0) __syncthreads();
        for (int i = tid; i < 800; i += 128) {
            float w = Kw[ci * 800 + i];
            ws2[i] = pack2(w, w);
        }
        __syncthreads();
#pragma unroll
        for (int kh = 0; kh < 5; kh++) {
            int ih = 2 * oh + kh - 1;  // -1..11
            bool rowok = (ih >= 0);
            const float* rowp = g_bufB + ((ci * 12 + ih) * 12) * BB + b;
            u64 r[13];  // r[j] holds iw = j-1 ; r[0] = 0 (iw = -1)
            r[0] = 0ULL;
#pragma unroll
            for (int j = 1; j < 13; j++) r[j] = rowok ? ldg2(rowp + (j - 1) * BB) : 0ULL;
#pragma unroll
            for (int kw = 0; kw < 5; kw++) {
                int base = (kh * 5 + kw) * 32 + co0;
#pragma unroll
                for (int co = 0; co < 8; co++) {
                    u64 w = ws2[base + co];
#pragma unroll
                    for (int ow = 0; ow < 5; ow++) fma2(acc[co][ow], r[2 * ow + kw], w);
                }
            }
        }
    }
#pragma unroll
    for (int co = 0; co < 8; co++)
#pragma unroll
        for (int ow = 0; ow < 5; ow++) {
            float2 v = unpack2(acc[co][ow]);
            *reinterpret_cast<float2*>(g_a6 + (((co0 + co) * 5 + oh) * 5 + ow) * BB + b) = v;
        }
}

// ---------------- FC (1152->10, only 800 nonzero inputs) + softmax -------------------------
__global__ void __launch_bounds__(256) fc_kernel(const float* __restrict__ Wfc,
                                                 const float* __restrict__ bfc,
                                                 float* __restrict__ out) {
    __shared__ __align__(16) float Wp[8000];  // [k'][cls], k' = co*25+oh*5+ow over valid 5x5
    __shared__ float red[4][64][10];
    int tid = threadIdx.x;
    for (int i = tid; i < 8000; i += 256) {
        int kp = i / 10, cls = i % 10;
        int co = kp / 25, rem = kp % 25, r = rem / 5, c = rem % 5;
        Wp[i] = Wfc[cls * 1152 + co * 36 + r * 6 + c];  // 6x6 layout, zeros at row/col 5
    }
    __syncthreads();
    const u64* Wp2 = reinterpret_cast<const u64*>(Wp);

    int bsub = tid & 63;
    int g = tid >> 6;  // k'-split group
    int b = blockIdx.x * 64 + bsub;

    u64 lg[5] = {0ULL, 0ULL, 0ULL, 0ULL, 0ULL};
    int k0 = g * 200;
    for (int kp = k0; kp < k0 + 200; kp++) {
        float v = g_a6[kp * BB + b];
        u64 v2 = pack2(v, v);
#pragma unroll
        for (int c = 0; c < 5; c++) fma2(lg[c], v2, Wp2[kp * 5 + c]);
    }
#pragma unroll
    for (int c = 0; c < 5; c++) {
        float2 f = unpack2(lg[c]);
        red[g][bsub][2 * c] = f.x;
        red[g][bsub][2 * c + 1] = f.y;
    }
    __syncthreads();
    if (g == 0) {
        float logits[10];
#pragma unroll
        for (int c = 0; c < 10; c++)
            logits[c] = red[0][bsub][c] + red[1][bsub][c] + red[2][bsub][c] + red[3][bsub][c] +
                        bfc[c];
        float m = logits[0];
#pragma unroll
        for (int c = 1; c < 10; c++) m = fmaxf(m, logits[c]);
        float s = 0.f;
#pragma unroll
        for (int c = 0; c < 10; c++) {
            float e = expf(logits[c] - m);
            logits[c] = e;
            s += e;
        }
        float inv = 1.f / s;
#pragma unroll
        for (int c = 0; c < 10; c++) out[b * 10 + c] = logits[c] * inv;
    }
}

// ---------------- launch -------------------------------------------------------------------
extern "C" void kernel_launch(void* const* d_in, const int* in_sizes, int n_in, void* d_out,
                              int out_size) {
    const float* x = (const float*)d_in[0];
    const float* K1 = (const float*)d_in[1];
    const float* K2 = (const float*)d_in[2];
    const float* K3 = (const float*)d_in[3];
    const float* K4 = (const float*)d_in[4];
    const float* K5 = (const float*)d_in[5];
    const float* K6 = (const float*)d_in[6];
    const float* Wfc = (const float*)d_in[7];
    const float* bfc = (const float*)d_in[8];
    float* out = (float*)d_out;

    transpose_kernel<<<dim3(74, 256), dim3(32, 8)>>>(x);
    conv1_kernel<<<dim3(128, 13), dim3(32, 3)>>>(K1);
    conv3_kernel<8, 13, 0, 1><<<dim3(128, 12), dim3(32, 6)>>>(K2);   // a1  -> bufA
    conv3_kernel<16, 12, 1, 2><<<dim3(128, 12), dim3(32, 6)>>>(K3);  // bufA -> bufB
    conv3_kernel<16, 12, 2, 1><<<dim3(128, 12), dim3(32, 6)>>>(K4);  // bufB -> bufA
    conv3_kernel<16, 12, 1, 2><<<dim3(128, 12), dim3(32, 6)>>>(K5);  // bufA -> bufB
    conv6_kernel<<<dim3(128, 5), dim3(32, 4)>>>(K6);                 // bufB -> a6
    fc_kernel<<<128, 256>>>(Wfc, bfc, out);
}

// round 6
// speedup vs baseline: 1.2312x; 1.1167x over previous
#include <cuda_runtime.h>
#include <math.h>

#define BB 8192

// ---------------- intermediate buffers ----------------------------------------------------
__device__ float g_xT[3 * 28 * 28 * BB];     // input transposed  [c][h][w][b]
__device__ float g_a1[8 * 13 * 13 * BB];     // layer1 out (full 13x13 valid)
__device__ float g_bufA[16 * 12 * 12 * BB];  // ping (compact 12x12 valid region)
__device__ float g_bufB[16 * 12 * 12 * BB];  // pong
__device__ float g_a6[32 * 5 * 5 * BB];      // layer6 out (compact 5x5 valid)

typedef unsigned long long u64;

// ---------------- f32x2 helpers -----------------------------------------------------------
__device__ __forceinline__ void fma2(u64& d, u64 a, u64 b) {
    asm("fma.rn.f32x2 %0, %1, %2, %0;" : "+l"(d) : "l"(a), "l"(b));
}
__device__ __forceinline__ u64 pack2(float lo, float hi) {
    u64 r;
    asm("mov.b64 %0, {%1, %2};" : "=l"(r) : "f"(lo), "f"(hi));
    return r;
}
__device__ __forceinline__ float2 unpack2(u64 v) {
    float2 f;
    asm("mov.b64 {%0, %1}, %2;" : "=f"(f.x), "=f"(f.y) : "l"(v));
    return f;
}
__device__ __forceinline__ u64 ldg2(const float* p) {
    return *reinterpret_cast<const u64*>(p);
}

// ---------------- transpose: x (B, 3*28*28) NCHW -> xT [c*h*w][B] --------------------------
__global__ void __launch_bounds__(256) transpose_kernel(const float* __restrict__ x) {
    __shared__ float tile[32][33];
    int p0 = blockIdx.x * 32;
    int b0 = blockIdx.y * 32;
    int tx = threadIdx.x, ty = threadIdx.y;  // (32, 8)
#pragma unroll
    for (int j = 0; j < 4; j++) {
        int p = p0 + tx;
        int bb = b0 + ty + 8 * j;
        tile[ty + 8 * j][tx] = (p < 2352) ? x[bb * 2352 + p] : 0.f;
    }
    __syncthreads();
#pragma unroll
    for (int j = 0; j < 4; j++) {
        int p = p0 + ty + 8 * j;
        int bb = b0 + tx;
        if (p < 2352) g_xT[p * BB + bb] = tile[tx][ty + 8 * j];
    }
}

// ---------------- layer 1: cin=3, k=5, s=2, pad=1, 28x28 -> 13x13, cout=8, ReLU ------------
// weights consumed in stored flat order: Kw[(ci*25 + kh*5 + kw)*8 + co]
template <int OWG>
__device__ __forceinline__ void conv1_body(const u64* __restrict__ ws2, int ow0, int b, int oh) {
    constexpr int S = 2 * OWG + 3;  // input span
    u64 acc[8][OWG];
#pragma unroll
    for (int co = 0; co < 8; co++)
#pragma unroll
        for (int ow = 0; ow < OWG; ow++) acc[co][ow] = 0ULL;

#pragma unroll 1
    for (int ci = 0; ci < 3; ci++) {
#pragma unroll 1
        for (int kh = 0; kh < 5; kh++) {
            int ih = 2 * oh + kh - 1;  // -1..27
            bool rowok = (ih >= 0) && (ih < 28);
            const float* rowp = g_xT + ((ci * 28 + ih) * 28 + (2 * ow0 - 1)) * BB + b;
            u64 r[S];
#pragma unroll
            for (int j = 0; j < S; j++) {
                int iw = 2 * ow0 - 1 + j;
                r[j] = (rowok && iw >= 0 && iw < 28) ? ldg2(rowp + j * BB) : 0ULL;
            }
#pragma unroll
            for (int kw = 0; kw < 5; kw++) {
                int base = ((ci * 5 + kh) * 5 + kw) * 8;
#pragma unroll
                for (int co = 0; co < 8; co++) {
                    u64 w = ws2[base + co];
#pragma unroll
                    for (int ow = 0; ow < OWG; ow++) fma2(acc[co][ow], r[2 * ow + kw], w);
                }
            }
        }
    }
#pragma unroll
    for (int co = 0; co < 8; co++)
#pragma unroll
        for (int ow = 0; ow < OWG; ow++) {
            float2 v = unpack2(acc[co][ow]);
            float2 o;
            o.x = fmaxf(v.x, 0.f);
            o.y = fmaxf(v.y, 0.f);
            *reinterpret_cast<float2*>(g_a1 + ((co * 13 + oh) * 13 + ow0 + ow) * BB + b) = o;
        }
}

__global__ void __launch_bounds__(96) conv1_kernel(const float* __restrict__ Kw) {
    __shared__ u64 ws2[600];
    int tid = threadIdx.y * 32 + threadIdx.x;
    for (int i = tid; i < 600; i += 96) {
        float w = Kw[i];
        ws2[i] = pack2(w, w);
    }
    __syncthreads();
    int b = blockIdx.x * 64 + threadIdx.x * 2;
    int oh = blockIdx.y;
    int ty = threadIdx.y;  // 0..2, warp-granular
    if (ty == 0) conv1_body<4>(ws2, 0, b, oh);
    else if (ty == 1) conv1_body<4>(ws2, 4, b, oh);
    else conv1_body<5>(ws2, 8, b, oh);
}

// ---------------- 3x3 layers (2..5): s=1, pad=1, out 12x12 valid, cout=16, ReLU ------------
// SRC/DST: 0 = g_a1, 1 = g_bufA, 2 = g_bufB
__device__ __forceinline__ float* buf_ptr(int id) {
    return id == 0 ? g_a1 : (id == 1 ? g_bufA : g_bufB);
}

template <int CIN, int IN_H, int SRC, int DST>
__global__ void __launch_bounds__(192, 3) conv3_kernel(const float* __restrict__ Kw) {
    constexpr int NW = CIN * 9 * 16;
    __shared__ u64 ws2[NW];
    int tid = threadIdx.y * 32 + threadIdx.x;
    for (int i = tid; i < NW; i += 192) {
        float w = Kw[i];
        ws2[i] = pack2(w, w);
    }
    __syncthreads();

    const float* in = buf_ptr(SRC);
    float* out = buf_ptr(DST);

    int ty = threadIdx.y;        // 0..5
    int co0 = (ty / 3) * 8;      // 8 output channels per thread
    int ow0 = (ty % 3) * 4;      // 4 output columns per thread
    int b = blockIdx.x * 64 + threadIdx.x * 2;
    int oh = blockIdx.y;

    u64 acc[8][4];
#pragma unroll
    for (int co = 0; co < 8; co++)
#pragma unroll
        for (int ow = 0; ow < 4; ow++) acc[co][ow] = 0ULL;

#pragma unroll 1
    for (int ci = 0; ci < CIN; ci++) {
#pragma unroll
        for (int kh = 0; kh < 3; kh++) {
            int ih = oh + kh - 1;  // -1..12 ; row IN_H..12 zero (quirk)
            bool rowok = (ih >= 0) && (ih < IN_H);
            const float* rowp = in + ((ci * IN_H + ih) * IN_H + (ow0 - 1)) * BB + b;
            u64 r[6];
#pragma unroll
            for (int j = 0; j < 6; j++) {
                int iw = ow0 - 1 + j;
                r[j] = (rowok && iw >= 0 && iw < IN_H) ? ldg2(rowp + j * BB) : 0ULL;
            }
#pragma unroll
            for (int kw = 0; kw < 3; kw++) {
                int base = ((ci * 3 + kh) * 3 + kw) * 16 + co0;
#pragma unroll
                for (int co = 0; co < 8; co++) {
                    u64 w = ws2[base + co];
#pragma unroll
                    for (int ow = 0; ow < 4; ow++) fma2(acc[co][ow], r[ow + kw], w);
                }
            }
        }
    }
#pragma unroll
    for (int co = 0; co < 8; co++)
#pragma unroll
        for (int ow = 0; ow < 4; ow++) {
            float2 v = unpack2(acc[co][ow]);
            float2 o;
            o.x = fmaxf(v.x, 0.f);
            o.y = fmaxf(v.y, 0.f);
            *reinterpret_cast<float2*>(out + (((co0 + co) * 12 + oh) * 12 + ow0 + ow) * BB + b) =
                o;
        }
}

// ---------------- layer 6: cin=16, k=5, s=2, pad=1, 12x12 -> 5x5 valid, cout=32, no ReLU ---
__global__ void __launch_bounds__(128) conv6_kernel(const float* __restrict__ Kw) {
    __shared__ u64 ws2[800];
    int tid = threadIdx.y * 32 + threadIdx.x;
    int co0 = threadIdx.y * 8;  // 8 of 32 output channels per thread
    int b = blockIdx.x * 64 + threadIdx.x * 2;
    int oh = blockIdx.y;  // 0..4

    u64 acc[8][5];
#pragma unroll
    for (int co = 0; co < 8; co++)
#pragma unroll
        for (int ow = 0; ow < 5; ow++) acc[co][ow] = 0ULL;

#pragma unroll 1
    for (int ci = 0; ci < 16; ci++) {
        if (ci > 0) __syncthreads();
        for (int i = tid; i < 800; i += 128) {
            float w = Kw[ci * 800 + i];
            ws2[i] = pack2(w, w);
        }
        __syncthreads();
#pragma unroll 1
        for (int kh = 0; kh < 5; kh++) {
            int ih = 2 * oh + kh - 1;  // -1..11
            bool rowok = (ih >= 0);
            const float* rowp = g_bufB + ((ci * 12 + ih) * 12) * BB + b;
            u64 r[13];  // r[j] holds iw = j-1 ; r[0] = 0 (iw = -1)
            r[0] = 0ULL;
#pragma unroll
            for (int j = 1; j < 13; j++) r[j] = rowok ? ldg2(rowp + (j - 1) * BB) : 0ULL;
#pragma unroll
            for (int kw = 0; kw < 5; kw++) {
                int base = (kh * 5 + kw) * 32 + co0;
#pragma unroll
                for (int co = 0; co < 8; co++) {
                    u64 w = ws2[base + co];
#pragma unroll
                    for (int ow = 0; ow < 5; ow++) fma2(acc[co][ow], r[2 * ow + kw], w);
                }
            }
        }
    }
#pragma unroll
    for (int co = 0; co < 8; co++)
#pragma unroll
        for (int ow = 0; ow < 5; ow++) {
            float2 v = unpack2(acc[co][ow]);
            *reinterpret_cast<float2*>(g_a6 + (((co0 + co) * 5 + oh) * 5 + ow) * BB + b) = v;
        }
}

// ---------------- FC (1152->10, only 800 nonzero inputs) + softmax -------------------------
__global__ void __launch_bounds__(256) fc_kernel(const float* __restrict__ Wfc,
                                                 const float* __restrict__ bfc,
                                                 float* __restrict__ out) {
    __shared__ __align__(16) float Wp[8000];  // [k'][cls], k' = co*25+oh*5+ow over valid 5x5
    __shared__ float red[4][64][10];
    int tid = threadIdx.x;
    for (int i = tid; i < 8000; i += 256) {
        int kp = i / 10, cls = i % 10;
        int co = kp / 25, rem = kp % 25, r = rem / 5, c = rem % 5;
        Wp[i] = Wfc[cls * 1152 + co * 36 + r * 6 + c];  // 6x6 layout, zeros at row/col 5
    }
    __syncthreads();
    const u64* Wp2 = reinterpret_cast<const u64*>(Wp);

    int bsub = tid & 63;
    int g = tid >> 6;  // k'-split group
    int b = blockIdx.x * 64 + bsub;

    u64 lg[5] = {0ULL, 0ULL, 0ULL, 0ULL, 0ULL};
    int k0 = g * 200;
#pragma unroll 4
    for (int kp = k0; kp < k0 + 200; kp++) {
        float v = g_a6[kp * BB + b];
        u64 v2 = pack2(v, v);
#pragma unroll
        for (int c = 0; c < 5; c++) fma2(lg[c], v2, Wp2[kp * 5 + c]);
    }
#pragma unroll
    for (int c = 0; c < 5; c++) {
        float2 f = unpack2(lg[c]);
        red[g][bsub][2 * c] = f.x;
        red[g][bsub][2 * c + 1] = f.y;
    }
    __syncthreads();
    if (g == 0) {
        float logits[10];
#pragma unroll
        for (int c = 0; c < 10; c++)
            logits[c] = red[0][bsub][c] + red[1][bsub][c] + red[2][bsub][c] + red[3][bsub][c] +
                        bfc[c];
        float m = logits[0];
#pragma unroll
        for (int c = 1; c < 10; c++) m = fmaxf(m, logits[c]);
        float s = 0.f;
#pragma unroll
        for (int c = 0; c < 10; c++) {
            float e = expf(logits[c] - m);
            logits[c] = e;
            s += e;
        }
        float inv = 1.f / s;
#pragma unroll
        for (int c = 0; c < 10; c++) out[b * 10 + c] = logits[c] * inv;
    }
}

// ---------------- launch -------------------------------------------------------------------
extern "C" void kernel_launch(void* const* d_in, const int* in_sizes, int n_in, void* d_out,
                              int out_size) {
    const float* x = (const float*)d_in[0];
    const float* K1 = (const float*)d_in[1];
    const float* K2 = (const float*)d_in[2];
    const float* K3 = (const float*)d_in[3];
    const float* K4 = (const float*)d_in[4];
    const float* K5 = (const float*)d_in[5];
    const float* K6 = (const float*)d_in[6];
    const float* Wfc = (const float*)d_in[7];
    const float* bfc = (const float*)d_in[8];
    float* out = (float*)d_out;

    transpose_kernel<<<dim3(74, 256), dim3(32, 8)>>>(x);
    conv1_kernel<<<dim3(128, 13), dim3(32, 3)>>>(K1);
    conv3_kernel<8, 13, 0, 1><<<dim3(128, 12), dim3(32, 6)>>>(K2);   // a1  -> bufA
    conv3_kernel<16, 12, 1, 2><<<dim3(128, 12), dim3(32, 6)>>>(K3);  // bufA -> bufB
    conv3_kernel<16, 12, 2, 1><<<dim3(128, 12), dim3(32, 6)>>>(K4);  // bufB -> bufA
    conv3_kernel<16, 12, 1, 2><<<dim3(128, 12), dim3(32, 6)>>>(K5);  // bufA -> bufB
    conv6_kernel<<<dim3(128, 5), dim3(32, 4)>>>(K6);                 // bufB -> a6
    fc_kernel<<<128, 256>>>(Wfc, bfc, out);
}

// round 7
// speedup vs baseline: 1.3802x; 1.1210x over previous
#include <cuda_runtime.h>
#include <math.h>

#define BB 8192

// ---------------- intermediate buffers (zero-initialized; halos stay zero forever) --------
// x padded to 30x30 (interior at +1). Conv outputs padded to 14x14 (interior at +1).
// The reference quirk (last row/col of layers 2-6 forced zero) is realized by storing only
// the 12x12 / 13x13 valid region; index 13 of bufA/bufB is halo zero = the quirk zeros.
__device__ float g_xT[3 * 30 * 30 * BB];    // [c][30][30][b]
__device__ float g_a1[8 * 14 * 14 * BB];    // layer1 out, 13x13 valid at idx 1..13
__device__ float g_bufA[16 * 14 * 14 * BB]; // ping, 12x12 valid at idx 1..12
__device__ float g_bufB[16 * 14 * 14 * BB]; // pong
__device__ float g_a6[32 * 5 * 5 * BB];     // layer6 out (compact 5x5 valid)

typedef unsigned long long u64;

// ---------------- f32x2 helpers -----------------------------------------------------------
__device__ __forceinline__ void fma2(u64& d, u64 a, u64 b) {
    asm("fma.rn.f32x2 %0, %1, %2, %0;" : "+l"(d) : "l"(a), "l"(b));
}
__device__ __forceinline__ u64 pack2(float lo, float hi) {
    u64 r;
    asm("mov.b64 %0, {%1, %2};" : "=l"(r) : "f"(lo), "f"(hi));
    return r;
}
__device__ __forceinline__ float2 unpack2(u64 v) {
    float2 f;
    asm("mov.b64 {%0, %1}, %2;" : "=f"(f.x), "=f"(f.y) : "l"(v));
    return f;
}
__device__ __forceinline__ u64 ldg2(const float* p) {
    return *reinterpret_cast<const u64*>(p);
}

// ---------------- transpose: x (B, 3*28*28) NCHW -> padded xT [c][30][30][B] ---------------
__global__ void __launch_bounds__(256) transpose_kernel(const float* __restrict__ x) {
    __shared__ float tile[32][33];
    int p0 = blockIdx.x * 32;
    int b0 = blockIdx.y * 32;
    int tx = threadIdx.x, ty = threadIdx.y;  // (32, 8)
#pragma unroll
    for (int j = 0; j < 4; j++) {
        int p = p0 + tx;
        int bb = b0 + ty + 8 * j;
        tile[ty + 8 * j][tx] = (p < 2352) ? x[bb * 2352 + p] : 0.f;
    }
    __syncthreads();
#pragma unroll
    for (int j = 0; j < 4; j++) {
        int p = p0 + ty + 8 * j;
        int bb = b0 + tx;
        if (p < 2352) {
            int c = p / 784, rem = p % 784;
            int h = rem / 28, w = rem % 28;
            g_xT[((c * 30 + h + 1) * 30 + (w + 1)) * BB + bb] = tile[tx][ty + 8 * j];
        }
    }
}

// ---------------- layer 1: cin=3, k=5, s=2, pad=1, 28x28 -> 13x13, cout=8, ReLU ------------
// weights in stored flat order: Kw[(ci*25 + kh*5 + kw)*8 + co]; halo removes all predication.
template <int OWG>
__device__ __forceinline__ void conv1_body(const u64* __restrict__ ws2, int ow0, int b, int oh) {
    constexpr int S = 2 * OWG + 3;  // input span
    u64 acc[8][OWG];
#pragma unroll
    for (int co = 0; co < 8; co++)
#pragma unroll
        for (int ow = 0; ow < OWG; ow++) acc[co][ow] = 0ULL;

#pragma unroll 1
    for (int ci = 0; ci < 3; ci++) {
#pragma unroll 1
        for (int kh = 0; kh < 5; kh++) {
            // padded row index = 2*oh + kh (covers ih=-1..27 -> 0..28), col base = 2*ow0
            const float* rowp = g_xT + ((ci * 30 + 2 * oh + kh) * 30 + 2 * ow0) * BB + b;
            u64 r[S];
#pragma unroll
            for (int j = 0; j < S; j++) r[j] = ldg2(rowp + j * BB);
#pragma unroll
            for (int kw = 0; kw < 5; kw++) {
                int base = ((ci * 5 + kh) * 5 + kw) * 8;
#pragma unroll
                for (int co = 0; co < 8; co++) {
                    u64 w = ws2[base + co];
#pragma unroll
                    for (int ow = 0; ow < OWG; ow++) fma2(acc[co][ow], r[2 * ow + kw], w);
                }
            }
        }
    }
#pragma unroll
    for (int co = 0; co < 8; co++)
#pragma unroll
        for (int ow = 0; ow < OWG; ow++) {
            float2 v = unpack2(acc[co][ow]);
            float2 o;
            o.x = fmaxf(v.x, 0.f);
            o.y = fmaxf(v.y, 0.f);
            *reinterpret_cast<float2*>(g_a1 + ((co * 14 + oh + 1) * 14 + ow0 + ow + 1) * BB + b) =
                o;
        }
}

__global__ void __launch_bounds__(96) conv1_kernel(const float* __restrict__ Kw) {
    __shared__ u64 ws2[600];
    int tid = threadIdx.y * 32 + threadIdx.x;
    for (int i = tid; i < 600; i += 96) {
        float w = Kw[i];
        ws2[i] = pack2(w, w);
    }
    __syncthreads();
    int b = blockIdx.x * 64 + threadIdx.x * 2;
    int oh = blockIdx.y;
    int ty = threadIdx.y;  // 0..2, warp-granular
    if (ty == 0) conv1_body<4>(ws2, 0, b, oh);
    else if (ty == 1) conv1_body<4>(ws2, 4, b, oh);
    else conv1_body<5>(ws2, 8, b, oh);
}

// ---------------- 3x3 layers (2..5): s=1, pad=1, 12x12 out, cout=16, ReLU ------------------
// Padded halo input -> branch-free; 3-buffer software pipeline hides LDG latency.
__device__ __forceinline__ float* buf_ptr(int id) {
    return id == 0 ? g_a1 : (id == 1 ? g_bufA : g_bufB);
}

#define C3_LOAD(r, ci, kr)                                               \
    {                                                                    \
        const float* _p = pbase + ((ci) * 196 + (kr) * 14) * BB;         \
        _Pragma("unroll") for (int j = 0; j < 6; j++) (r)[j] =           \
            ldg2(_p + j * BB);                                           \
    }

#define C3_COMP(r, ci, kh)                                                        \
    {                                                                             \
        _Pragma("unroll") for (int kw = 0; kw < 3; kw++) {                        \
            int _base = (((ci) * 3 + (kh)) * 3 + kw) * 16 + co0;                  \
            _Pragma("unroll") for (int co = 0; co < 8; co++) {                    \
                u64 _w = ws2[_base + co];                                         \
                _Pragma("unroll") for (int ow = 0; ow < 4; ow++)                  \
                    fma2(acc[co][ow], (r)[ow + kw], _w);                          \
            }                                                                     \
        }                                                                         \
    }

template <int CIN, int SRC, int DST>
__global__ void __launch_bounds__(192) conv3_kernel(const float* __restrict__ Kw) {
    constexpr int NW = CIN * 144;
    __shared__ u64 ws2[NW];
    int tid = threadIdx.y * 32 + threadIdx.x;
    for (int i = tid; i < NW; i += 192) {
        float w = Kw[i];
        ws2[i] = pack2(w, w);
    }
    __syncthreads();

    const float* in = buf_ptr(SRC);
    float* out = buf_ptr(DST);

    int ty = threadIdx.y;    // 0..5
    int co0 = (ty / 3) * 8;  // 8 output channels per thread
    int ow0 = (ty % 3) * 4;  // 4 output columns per thread
    int b = blockIdx.x * 64 + threadIdx.x * 2;
    int oh = blockIdx.y;

    // rows read: padded idx oh..oh+2 ; cols: padded idx ow0..ow0+5 (iw=-1 -> idx 0)
    const float* pbase = in + (oh * 14 + ow0) * BB + b;

    u64 acc[8][4];
#pragma unroll
    for (int co = 0; co < 8; co++)
#pragma unroll
        for (int ow = 0; ow < 4; ow++) acc[co][ow] = 0ULL;

    u64 rA[6], rB[6], rC[6];
    C3_LOAD(rA, 0, 0);
    C3_LOAD(rB, 0, 1);
#pragma unroll 1
    for (int ci = 0; ci < CIN; ci++) {
        int cn = (ci + 1 < CIN) ? ci + 1 : ci;  // clamped prefetch target
        C3_LOAD(rC, ci, 2);
        C3_COMP(rA, ci, 0);
        C3_LOAD(rA, cn, 0);
        C3_COMP(rB, ci, 1);
        C3_LOAD(rB, cn, 1);
        C3_COMP(rC, ci, 2);
    }
#pragma unroll
    for (int co = 0; co < 8; co++)
#pragma unroll
        for (int ow = 0; ow < 4; ow++) {
            float2 v = unpack2(acc[co][ow]);
            float2 o;
            o.x = fmaxf(v.x, 0.f);
            o.y = fmaxf(v.y, 0.f);
            *reinterpret_cast<float2*>(out +
                                       (((co0 + co) * 14 + oh + 1) * 14 + ow0 + ow + 1) * BB + b) =
                o;
        }
}

// ---------------- layer 6: cin=16, k=5, s=2, pad=1, 12x12 -> 5x5 valid, cout=32, no ReLU ---
// 256 threads (8 warps): co split 8-way; weights staged in chunks of 4 ci.
__global__ void __launch_bounds__(256) conv6_kernel(const float* __restrict__ Kw) {
    __shared__ u64 ws2[3200];  // 4 ci * 800
    int tid = threadIdx.y * 32 + threadIdx.x;
    int co0 = threadIdx.y * 4;  // 4 of 32 output channels per thread
    int b = blockIdx.x * 64 + threadIdx.x * 2;
    int oh = blockIdx.y;  // 0..4

    u64 acc[4][5];
#pragma unroll
    for (int co = 0; co < 4; co++)
#pragma unroll
        for (int ow = 0; ow < 5; ow++) acc[co][ow] = 0ULL;

#pragma unroll 1
    for (int cc = 0; cc < 4; cc++) {
        if (cc > 0) __syncthreads();
        for (int i = tid; i < 3200; i += 256) {
            float w = Kw[cc * 3200 + i];
            ws2[i] = pack2(w, w);
        }
        __syncthreads();
#pragma unroll 1
        for (int c4 = 0; c4 < 4; c4++) {
            int ci = cc * 4 + c4;
#pragma unroll 1
            for (int kh = 0; kh < 5; kh++) {
                // padded row idx = 2*oh + kh (ih=-1..11 -> 0..12); col idx 0..12
                const float* rowp = g_bufB + ((ci * 14 + 2 * oh + kh) * 14) * BB + b;
                u64 r[13];
#pragma unroll
                for (int j = 0; j < 13; j++) r[j] = ldg2(rowp + j * BB);
#pragma unroll
                for (int kw = 0; kw < 5; kw++) {
                    int base = (c4 * 25 + kh * 5 + kw) * 32 + co0;
#pragma unroll
                    for (int co = 0; co < 4; co++) {
                        u64 w = ws2[base + co];
#pragma unroll
                        for (int ow = 0; ow < 5; ow++) fma2(acc[co][ow], r[2 * ow + kw], w);
                    }
                }
            }
        }
    }
#pragma unroll
    for (int co = 0; co < 4; co++)
#pragma unroll
        for (int ow = 0; ow < 5; ow++) {
            float2 v = unpack2(acc[co][ow]);
            *reinterpret_cast<float2*>(g_a6 + (((co0 + co) * 5 + oh) * 5 + ow) * BB + b) = v;
        }
}

// ---------------- FC (1152->10, only 800 nonzero inputs) + softmax -------------------------
__global__ void __launch_bounds__(256) fc_kernel(const float* __restrict__ Wfc,
                                                 const float* __restrict__ bfc,
                                                 float* __restrict__ out) {
    __shared__ __align__(16) float Wp[8000];  // [k'][cls], k' = co*25+oh*5+ow over valid 5x5
    __shared__ float red[4][64][10];
    int tid = threadIdx.x;
    for (int i = tid; i < 8000; i += 256) {
        int kp = i / 10, cls = i % 10;
        int co = kp / 25, rem = kp % 25, r = rem / 5, c = rem % 5;
        Wp[i] = Wfc[cls * 1152 + co * 36 + r * 6 + c];  // 6x6 layout, zeros at row/col 5
    }
    __syncthreads();
    const u64* Wp2 = reinterpret_cast<const u64*>(Wp);

    int bsub = tid & 63;
    int g = tid >> 6;  // k'-split group
    int b = blockIdx.x * 64 + bsub;

    u64 lg[5] = {0ULL, 0ULL, 0ULL, 0ULL, 0ULL};
    int k0 = g * 200;
#pragma unroll 4
    for (int kp = k0; kp < k0 + 200; kp++) {
        float v = g_a6[kp * BB + b];
        u64 v2 = pack2(v, v);
#pragma unroll
        for (int c = 0; c < 5; c++) fma2(lg[c], v2, Wp2[kp * 5 + c]);
    }
#pragma unroll
    for (int c = 0; c < 5; c++) {
        float2 f = unpack2(lg[c]);
        red[g][bsub][2 * c] = f.x;
        red[g][bsub][2 * c + 1] = f.y;
    }
    __syncthreads();
    if (g == 0) {
        float logits[10];
#pragma unroll
        for (int c = 0; c < 10; c++)
            logits[c] = red[0][bsub][c] + red[1][bsub][c] + red[2][bsub][c] + red[3][bsub][c] +
                        bfc[c];
        float m = logits[0];
#pragma unroll
        for (int c = 1; c < 10; c++) m = fmaxf(m, logits[c]);
        float s = 0.f;
#pragma unroll
        for (int c = 0; c < 10; c++) {
            float e = expf(logits[c] - m);
            logits[c] = e;
            s += e;
        }
        float inv = 1.f / s;
#pragma unroll
        for (int c = 0; c < 10; c++) out[b * 10 + c] = logits[c] * inv;
    }
}

// ---------------- launch -------------------------------------------------------------------
extern "C" void kernel_launch(void* const* d_in, const int* in_sizes, int n_in, void* d_out,
                              int out_size) {
    const float* x = (const float*)d_in[0];
    const float* K1 = (const float*)d_in[1];
    const float* K2 = (const float*)d_in[2];
    const float* K3 = (const float*)d_in[3];
    const float* K4 = (const float*)d_in[4];
    const float* K5 = (const float*)d_in[5];
    const float* K6 = (const float*)d_in[6];
    const float* Wfc = (const float*)d_in[7];
    const float* bfc = (const float*)d_in[8];
    float* out = (float*)d_out;

    transpose_kernel<<<dim3(74, 256), dim3(32, 8)>>>(x);
    conv1_kernel<<<dim3(128, 13), dim3(32, 3)>>>(K1);
    conv3_kernel<8, 0, 1><<<dim3(128, 12), dim3(32, 6)>>>(K2);   // a1  -> bufA
    conv3_kernel<16, 1, 2><<<dim3(128, 12), dim3(32, 6)>>>(K3);  // bufA -> bufB
    conv3_kernel<16, 2, 1><<<dim3(128, 12), dim3(32, 6)>>>(K4);  // bufB -> bufA
    conv3_kernel<16, 1, 2><<<dim3(128, 12), dim3(32, 6)>>>(K5);  // bufA -> bufB
    conv6_kernel<<<dim3(128, 5), dim3(32, 8)>>>(K6);             // bufB -> a6
    fc_kernel<<<128, 256>>>(Wfc, bfc, out);
}

// round 8
// speedup vs baseline: 1.4822x; 1.0739x over previous
#include <cuda_runtime.h>
#include <math.h>

#define BB 8192

// ---------------- intermediate buffers (zero-initialized; halos stay zero forever) --------
__device__ float g_xT[3 * 30 * 30 * BB];    // [c][30][30][b], 28x28 valid at idx 1..28
__device__ float g_a1[8 * 14 * 14 * BB];    // layer1 out, 13x13 valid at idx 1..13
__device__ float g_bufA[16 * 14 * 14 * BB]; // ping, 12x12 valid at idx 1..12
__device__ float g_bufB[16 * 14 * 14 * BB]; // pong
__device__ float g_a6[32 * 5 * 5 * BB];     // layer6 out (compact 5x5 valid)

typedef unsigned long long u64;

// ---------------- f32x2 helpers -----------------------------------------------------------
__device__ __forceinline__ void fma2(u64& d, u64 a, u64 b) {
    asm("fma.rn.f32x2 %0, %1, %2, %0;" : "+l"(d) : "l"(a), "l"(b));
}
__device__ __forceinline__ u64 pack2(float lo, float hi) {
    u64 r;
    asm("mov.b64 %0, {%1, %2};" : "=l"(r) : "f"(lo), "f"(hi));
    return r;
}
__device__ __forceinline__ float2 unpack2(u64 v) {
    float2 f;
    asm("mov.b64 {%0, %1}, %2;" : "=f"(f.x), "=f"(f.y) : "l"(v));
    return f;
}
__device__ __forceinline__ u64 ldg2(const float* p) {
    return *reinterpret_cast<const u64*>(p);
}

// ---------------- transpose: x (B, 3*28*28) NCHW -> padded xT [c][30][30][B] ---------------
__global__ void __launch_bounds__(256) transpose_kernel(const float* __restrict__ x) {
    __shared__ float tile[32][33];
    int p0 = blockIdx.x * 32;
    int b0 = blockIdx.y * 32;
    int tx = threadIdx.x, ty = threadIdx.y;  // (32, 8)
#pragma unroll
    for (int j = 0; j < 4; j++) {
        int p = p0 + tx;
        int bb = b0 + ty + 8 * j;
        tile[ty + 8 * j][tx] = (p < 2352) ? x[bb * 2352 + p] : 0.f;
    }
    __syncthreads();
#pragma unroll
    for (int j = 0; j < 4; j++) {
        int p = p0 + ty + 8 * j;
        int bb = b0 + tx;
        if (p < 2352) {
            int c = p / 784, rem = p % 784;
            int h = rem / 28, w = rem % 28;
            g_xT[((c * 30 + h + 1) * 30 + (w + 1)) * BB + bb] = tile[tx][ty + 8 * j];
        }
    }
}

// ---------------- layer 1: cin=3, k=5, s=2, pad=1, 28x28 -> 13x13, cout=8, ReLU ------------
// weights in stored flat order: Kw[(ci*25 + kh*5 + kw)*8 + co]; halo removes all predication.
template <int OWG>
__device__ __forceinline__ void conv1_body(const u64* __restrict__ ws2, int ow0, int b, int oh) {
    constexpr int S = 2 * OWG + 3;  // input span
    u64 acc[8][OWG];
#pragma unroll
    for (int co = 0; co < 8; co++)
#pragma unroll
        for (int ow = 0; ow < OWG; ow++) acc[co][ow] = 0ULL;

#pragma unroll 1
    for (int ci = 0; ci < 3; ci++) {
#pragma unroll
        for (int kh = 0; kh < 5; kh++) {
            const float* rowp = g_xT + ((ci * 30 + 2 * oh + kh) * 30 + 2 * ow0) * BB + b;
            u64 r[S];
#pragma unroll
            for (int j = 0; j < S; j++) r[j] = ldg2(rowp + j * BB);
#pragma unroll
            for (int kw = 0; kw < 5; kw++) {
                int base = ((ci * 5 + kh) * 5 + kw) * 8;
                ulonglong2 w01 = *reinterpret_cast<const ulonglong2*>(ws2 + base);
                ulonglong2 w23 = *reinterpret_cast<const ulonglong2*>(ws2 + base + 2);
                ulonglong2 w45 = *reinterpret_cast<const ulonglong2*>(ws2 + base + 4);
                ulonglong2 w67 = *reinterpret_cast<const ulonglong2*>(ws2 + base + 6);
#pragma unroll
                for (int ow = 0; ow < OWG; ow++) {
                    u64 v = r[2 * ow + kw];
                    fma2(acc[0][ow], v, w01.x);
                    fma2(acc[1][ow], v, w01.y);
                    fma2(acc[2][ow], v, w23.x);
                    fma2(acc[3][ow], v, w23.y);
                    fma2(acc[4][ow], v, w45.x);
                    fma2(acc[5][ow], v, w45.y);
                    fma2(acc[6][ow], v, w67.x);
                    fma2(acc[7][ow], v, w67.y);
                }
            }
        }
    }
#pragma unroll
    for (int co = 0; co < 8; co++)
#pragma unroll
        for (int ow = 0; ow < OWG; ow++) {
            float2 v = unpack2(acc[co][ow]);
            float2 o;
            o.x = fmaxf(v.x, 0.f);
            o.y = fmaxf(v.y, 0.f);
            *reinterpret_cast<float2*>(g_a1 + ((co * 14 + oh + 1) * 14 + ow0 + ow + 1) * BB + b) =
                o;
        }
}

__global__ void __launch_bounds__(96) conv1_kernel(const float* __restrict__ Kw) {
    __shared__ __align__(16) u64 ws2[600];
    int tid = threadIdx.y * 32 + threadIdx.x;
    for (int i = tid; i < 600; i += 96) {
        float w = Kw[i];
        ws2[i] = pack2(w, w);
    }
    __syncthreads();
    int b = blockIdx.x * 64 + threadIdx.x * 2;
    int oh = blockIdx.y;
    int ty = threadIdx.y;  // 0..2, warp-granular
    if (ty == 0) conv1_body<4>(ws2, 0, b, oh);
    else if (ty == 1) conv1_body<4>(ws2, 4, b, oh);
    else conv1_body<5>(ws2, 8, b, oh);
}

// ---------------- 3x3 layers (2..5): s=1, pad=1, 12x12 out, cout=16, ReLU ------------------
// 4co x 6ow per thread; LDS.128 weight pairs; 3-buffer row pipeline; halo = branch-free.
__device__ __forceinline__ float* buf_ptr(int id) {
    return id == 0 ? g_a1 : (id == 1 ? g_bufA : g_bufB);
}

#define C3_LOAD(r, ci, kr)                                           \
    {                                                                \
        const float* _p = pbase + ((ci) * 196 + (kr) * 14) * BB;     \
        _Pragma("unroll") for (int j = 0; j < 8; j++) (r)[j] =       \
            ldg2(_p + j * BB);                                       \
    }

#define C3_COMP(r, ci, kh)                                                          \
    {                                                                               \
        _Pragma("unroll") for (int kw = 0; kw < 3; kw++) {                          \
            int _base = (((ci) * 3 + (kh)) * 3 + kw) * 16 + co0;                    \
            ulonglong2 _w01 = *reinterpret_cast<const ulonglong2*>(ws2 + _base);    \
            ulonglong2 _w23 = *reinterpret_cast<const ulonglong2*>(ws2 + _base + 2);\
            _Pragma("unroll") for (int ow = 0; ow < 6; ow++) {                      \
                u64 _v = (r)[ow + kw];                                              \
                fma2(acc[0][ow], _v, _w01.x);                                       \
                fma2(acc[1][ow], _v, _w01.y);                                       \
                fma2(acc[2][ow], _v, _w23.x);                                       \
                fma2(acc[3][ow], _v, _w23.y);                                       \
            }                                                                       \
        }                                                                           \
    }

template <int CIN, int SRC, int DST>
__global__ void __launch_bounds__(256, 2) conv3_kernel(const float* __restrict__ Kw) {
    constexpr int NW = CIN * 144;
    __shared__ __align__(16) u64 ws2[NW];
    int tid = threadIdx.y * 32 + threadIdx.x;
    for (int i = tid; i < NW; i += 256) {
        float w = Kw[i];
        ws2[i] = pack2(w, w);
    }
    __syncthreads();

    const float* in = buf_ptr(SRC);
    float* out = buf_ptr(DST);

    int ty = threadIdx.y;      // 0..7
    int co0 = (ty & 3) * 4;    // 4 output channels per thread
    int ow0 = (ty >> 2) * 6;   // 6 output columns per thread (0 or 6)
    int b = blockIdx.x * 64 + threadIdx.x * 2;
    int oh = blockIdx.y;

    // rows read: padded idx oh..oh+2 ; cols: padded idx ow0..ow0+7
    const float* pbase = in + (oh * 14 + ow0) * BB + b;

    u64 acc[4][6];
#pragma unroll
    for (int co = 0; co < 4; co++)
#pragma unroll
        for (int ow = 0; ow < 6; ow++) acc[co][ow] = 0ULL;

    u64 rA[8], rB[8], rC[8];
    C3_LOAD(rA, 0, 0);
    C3_LOAD(rB, 0, 1);
#pragma unroll 1
    for (int ci = 0; ci < CIN; ci++) {
        int cn = (ci + 1 < CIN) ? ci + 1 : ci;  // clamped prefetch target
        C3_LOAD(rC, ci, 2);
        C3_COMP(rA, ci, 0);
        C3_LOAD(rA, cn, 0);
        C3_COMP(rB, ci, 1);
        C3_LOAD(rB, cn, 1);
        C3_COMP(rC, ci, 2);
    }
#pragma unroll
    for (int co = 0; co < 4; co++)
#pragma unroll
        for (int ow = 0; ow < 6; ow++) {
            float2 v = unpack2(acc[co][ow]);
            float2 o;
            o.x = fmaxf(v.x, 0.f);
            o.y = fmaxf(v.y, 0.f);
            *reinterpret_cast<float2*>(out +
                                       (((co0 + co) * 14 + oh + 1) * 14 + ow0 + ow + 1) * BB + b) =
                o;
        }
}

// ---------------- layer 6: cin=16, k=5, s=2, pad=1, 12x12 -> 5x5 valid, cout=32, no ReLU ---
// 256 threads (8 warps): 4co x 5ow; kh fully unrolled so ptxas pipelines row loads.
__global__ void __launch_bounds__(256, 2) conv6_kernel(const float* __restrict__ Kw) {
    __shared__ __align__(16) u64 ws2[3200];  // 4 ci * 800
    int tid = threadIdx.y * 32 + threadIdx.x;
    int co0 = threadIdx.y * 4;  // 4 of 32 output channels per thread
    int b = blockIdx.x * 64 + threadIdx.x * 2;
    int oh = blockIdx.y;  // 0..4

    u64 acc[4][5];
#pragma unroll
    for (int co = 0; co < 4; co++)
#pragma unroll
        for (int ow = 0; ow < 5; ow++) acc[co][ow] = 0ULL;

#pragma unroll 1
    for (int cc = 0; cc < 4; cc++) {
        if (cc > 0) __syncthreads();
        for (int i = tid; i < 3200; i += 256) {
            float w = Kw[cc * 3200 + i];
            ws2[i] = pack2(w, w);
        }
        __syncthreads();
#pragma unroll 1
        for (int c4 = 0; c4 < 4; c4++) {
            int ci = cc * 4 + c4;
#pragma unroll
            for (int kh = 0; kh < 5; kh++) {
                // padded row idx = 2*oh + kh (ih=-1..11 -> 0..12); col idx 0..12
                const float* rowp = g_bufB + ((ci * 14 + 2 * oh + kh) * 14) * BB + b;
                u64 r[13];
#pragma unroll
                for (int j = 0; j < 13; j++) r[j] = ldg2(rowp + j * BB);
#pragma unroll
                for (int kw = 0; kw < 5; kw++) {
                    int base = (c4 * 25 + kh * 5 + kw) * 32 + co0;
                    ulonglong2 w01 = *reinterpret_cast<const ulonglong2*>(ws2 + base);
                    ulonglong2 w23 = *reinterpret_cast<const ulonglong2*>(ws2 + base + 2);
#pragma unroll
                    for (int ow = 0; ow < 5; ow++) {
                        u64 v = r[2 * ow + kw];
                        fma2(acc[0][ow], v, w01.x);
                        fma2(acc[1][ow], v, w01.y);
                        fma2(acc[2][ow], v, w23.x);
                        fma2(acc[3][ow], v, w23.y);
                    }
                }
            }
        }
    }
#pragma unroll
    for (int co = 0; co < 4; co++)
#pragma unroll
        for (int ow = 0; ow < 5; ow++) {
            float2 v = unpack2(acc[co][ow]);
            *reinterpret_cast<float2*>(g_a6 + (((co0 + co) * 5 + oh) * 5 + ow) * BB + b) = v;
        }
}

// ---------------- FC (1152->10, only 800 nonzero inputs) + softmax -------------------------
__global__ void __launch_bounds__(256) fc_kernel(const float* __restrict__ Wfc,
                                                 const float* __restrict__ bfc,
                                                 float* __restrict__ out) {
    __shared__ __align__(16) float Wp[8000];  // [k'][cls], k' = co*25+oh*5+ow over valid 5x5
    __shared__ float red[4][64][10];
    int tid = threadIdx.x;
    for (int i = tid; i < 8000; i += 256) {
        int kp = i / 10, cls = i % 10;
        int co = kp / 25, rem = kp % 25, r = rem / 5, c = rem % 5;
        Wp[i] = Wfc[cls * 1152 + co * 36 + r * 6 + c];  // 6x6 layout, zeros at row/col 5
    }
    __syncthreads();
    const u64* Wp2 = reinterpret_cast<const u64*>(Wp);

    int bsub = tid & 63;
    int g = tid >> 6;  // k'-split group
    int b = blockIdx.x * 64 + bsub;

    u64 lg[5] = {0ULL, 0ULL, 0ULL, 0ULL, 0ULL};
    int k0 = g * 200;
#pragma unroll 4
    for (int kp = k0; kp < k0 + 200; kp++) {
        float v = g_a6[kp * BB + b];
        u64 v2 = pack2(v, v);
#pragma unroll
        for (int c = 0; c < 5; c++) fma2(lg[c], v2, Wp2[kp * 5 + c]);
    }
#pragma unroll
    for (int c = 0; c < 5; c++) {
        float2 f = unpack2(lg[c]);
        red[g][bsub][2 * c] = f.x;
        red[g][bsub][2 * c + 1] = f.y;
    }
    __syncthreads();
    if (g == 0) {
        float logits[10];
#pragma unroll
        for (int c = 0; c < 10; c++)
            logits[c] = red[0][bsub][c] + red[1][bsub][c] + red[2][bsub][c] + red[3][bsub][c] +
                        bfc[c];
        float m = logits[0];
#pragma unroll
        for (int c = 1; c < 10; c++) m = fmaxf(m, logits[c]);
        float s = 0.f;
#pragma unroll
        for (int c = 0; c < 10; c++) {
            float e = expf(logits[c] - m);
            logits[c] = e;
            s += e;
        }
        float inv = 1.f / s;
#pragma unroll
        for (int c = 0; c < 10; c++) out[b * 10 + c] = logits[c] * inv;
    }
}

// ---------------- launch -------------------------------------------------------------------
extern "C" void kernel_launch(void* const* d_in, const int* in_sizes, int n_in, void* d_out,
                              int out_size) {
    const float* x = (const float*)d_in[0];
    const float* K1 = (const float*)d_in[1];
    const float* K2 = (const float*)d_in[2];
    const float* K3 = (const float*)d_in[3];
    const float* K4 = (const float*)d_in[4];
    const float* K5 = (const float*)d_in[5];
    const float* K6 = (const float*)d_in[6];
    const float* Wfc = (const float*)d_in[7];
    const float* bfc = (const float*)d_in[8];
    float* out = (float*)d_out;

    transpose_kernel<<<dim3(74, 256), dim3(32, 8)>>>(x);
    conv1_kernel<<<dim3(128, 13), dim3(32, 3)>>>(K1);
    conv3_kernel<8, 0, 1><<<dim3(128, 12), dim3(32, 8)>>>(K2);   // a1  -> bufA
    conv3_kernel<16, 1, 2><<<dim3(128, 12), dim3(32, 8)>>>(K3);  // bufA -> bufB
    conv3_kernel<16, 2, 1><<<dim3(128, 12), dim3(32, 8)>>>(K4);  // bufB -> bufA
    conv3_kernel<16, 1, 2><<<dim3(128, 12), dim3(32, 8)>>>(K5);  // bufA -> bufB
    conv6_kernel<<<dim3(128, 5), dim3(32, 8)>>>(K6);             // bufB -> a6
    fc_kernel<<<128, 256>>>(Wfc, bfc, out);
}